// round 5
// baseline (speedup 1.0000x reference)
#include <cuda_runtime.h>
#include <cuda_bf16.h>
#include <cstdint>
#include <cstddef>

#define Ss 2048
#define Dd 512
#define Hh 8
#define DKk 64
#define BH 16
#define MM 4096
#define SCALE 0.125f

// ---------------- scratch (device globals; no allocation allowed) ----------------
__device__ __nv_bfloat16 g_in_hi[3][MM * Dd], g_in_lo[3][MM * Dd];   // converted inputs
__device__ __nv_bfloat16 g_w_hi[4][Dd * Dd],  g_w_lo[4][Dd * Dd];    // converted weights
__device__ __nv_bfloat16 g_Qhi[BH * Ss * DKk], g_Qlo[BH * Ss * DKk];
__device__ __nv_bfloat16 g_Khi[BH * Ss * DKk], g_Klo[BH * Ss * DKk];
__device__ __nv_bfloat16 g_Vthi[BH * DKk * Ss], g_Vtlo[BH * DKk * Ss]; // [b,h,dk,s]
__device__ __nv_bfloat16 g_Ohi[MM * Dd], g_Olo[MM * Dd];             // merged heads
__device__ float g_lpart[BH * Ss * 64];
__device__ float g_invl[BH * Ss];

// ---------------- helpers ----------------
__device__ __forceinline__ uint32_t pack_bf2(__nv_bfloat16 a, __nv_bfloat16 b) {
    __nv_bfloat162 t; t.x = a; t.y = b;
    return *reinterpret_cast<uint32_t*>(&t);
}
__device__ __forceinline__ void hilo(float f0, float f1, uint32_t& hi, uint32_t& lo) {
    __nv_bfloat16 ha = __float2bfloat16(f0);
    __nv_bfloat16 hb = __float2bfloat16(f1);
    hi = pack_bf2(ha, hb);
    lo = pack_bf2(__float2bfloat16(f0 - __bfloat162float(ha)),
                  __float2bfloat16(f1 - __bfloat162float(hb)));
}
__device__ __forceinline__ void mma_bf16(float& c0, float& c1, float& c2, float& c3,
                                         uint32_t a0, uint32_t a1, uint32_t a2, uint32_t a3,
                                         uint32_t b0, uint32_t b1) {
    asm volatile(
        "mma.sync.aligned.m16n8k16.row.col.f32.bf16.bf16.f32 "
        "{%0,%1,%2,%3}, {%4,%5,%6,%7}, {%8,%9}, {%0,%1,%2,%3};"
        : "+f"(c0), "+f"(c1), "+f"(c2), "+f"(c3)
        : "r"(a0), "r"(a1), "r"(a2), "r"(a3), "r"(b0), "r"(b1));
}
__device__ __forceinline__ void ldsm4(uint32_t* r, uint32_t addr) {
    asm volatile("ldmatrix.sync.aligned.m8n8.x4.shared.b16 {%0,%1,%2,%3}, [%4];"
                 : "=r"(r[0]), "=r"(r[1]), "=r"(r[2]), "=r"(r[3]) : "r"(addr));
}

// One KT=32 chunk of MMAs (2 k16 steps) with ldmatrix fragment loads.
__device__ __forceinline__ void mma_chunk(
    uint32_t sAhi, uint32_t sAlo, uint32_t sBhi, uint32_t sBlo,
    uint32_t offA0, uint32_t offA1, uint32_t offB0, uint32_t offB1,
    float acc[2][4][4])
{
#pragma unroll
    for (int s = 0; s < 2; s++) {
        const uint32_t so = s * 32;   // 8 words per k16 step
        uint32_t ah[2][4], al[2][4], bh2[2][4], bl2[2][4];
        ldsm4(ah[0], sAhi + offA0 + so);
        ldsm4(ah[1], sAhi + offA1 + so);
        ldsm4(al[0], sAlo + offA0 + so);
        ldsm4(al[1], sAlo + offA1 + so);
        ldsm4(bh2[0], sBhi + offB0 + so);
        ldsm4(bh2[1], sBhi + offB1 + so);
        ldsm4(bl2[0], sBlo + offB0 + so);
        ldsm4(bl2[1], sBlo + offB1 + so);
#pragma unroll
        for (int t = 0; t < 2; t++)
#pragma unroll
            for (int nt = 0; nt < 4; nt++) {
                float* cc = acc[t][nt];
                uint32_t b0h = bh2[nt >> 1][(nt & 1) * 2], b1h = bh2[nt >> 1][(nt & 1) * 2 + 1];
                uint32_t b0l = bl2[nt >> 1][(nt & 1) * 2], b1l = bl2[nt >> 1][(nt & 1) * 2 + 1];
                mma_bf16(cc[0], cc[1], cc[2], cc[3],
                         ah[t][0], ah[t][1], ah[t][2], ah[t][3], b0h, b1h);
                mma_bf16(cc[0], cc[1], cc[2], cc[3],
                         ah[t][0], ah[t][1], ah[t][2], ah[t][3], b0l, b1l);
                mma_bf16(cc[0], cc[1], cc[2], cc[3],
                         al[t][0], al[t][1], al[t][2], al[t][3], b0h, b1h);
            }
    }
}

// ---------------- elementwise pre-convert: f32 -> bf16 hi/lo planes ----------------
__global__ __launch_bounds__(256) void conv_hilo(const float* __restrict__ x,
                                                 __nv_bfloat16* __restrict__ hi,
                                                 __nv_bfloat16* __restrict__ lo)
{
    size_t i = ((size_t)blockIdx.x * 256 + threadIdx.x) * 4;
    float4 v = *(const float4*)&x[i];
    uint32_t h0, l0, h1, l1;
    hilo(v.x, v.y, h0, l0);
    hilo(v.z, v.w, h1, l1);
    *(uint2*)(hi + i) = make_uint2(h0, h1);
    *(uint2*)(lo + i) = make_uint2(l0, l1);
}

// =====================================================================
// Unified GEMM: C[m,n] = sum_k A[m,k] * B[n,k]   (both operands k-contiguous)
// Block tile 128x64, KT=32 chunks, 8 warps (4m x 2n), warp tile 32x32.
// MODE 0: A/B planes -> QK head-split planes
// MODE 1: A/B planes -> Vt planes
// MODE 2: A/B planes -> f32 [m, Dd]
// MODE 3: Q/K planes (per bh) -> P~ = exp(s/8) f32 + lpart
// MODE 4: A = P~ f32 (normalize + writeback), B = Vt planes -> O planes
// =====================================================================
template <int MODE>
__global__ __launch_bounds__(256) void gemm_k(
    const __nv_bfloat16* __restrict__ Ahi, const __nv_bfloat16* __restrict__ Alo,
    const __nv_bfloat16* __restrict__ Bhi, const __nv_bfloat16* __restrict__ Blo,
    float* __restrict__ Pf, float* __restrict__ Cf,
    __nv_bfloat16* __restrict__ Ohi, __nv_bfloat16* __restrict__ Olo,
    const float* __restrict__ invl, float* __restrict__ lpart,
    int K, int lda, int ldb)
{
    int bh = 0, b_ = 0, h_ = 0;
    if (MODE == 3) {
        bh = blockIdx.z;
        Ahi += (size_t)bh * Ss * DKk; Alo += (size_t)bh * Ss * DKk;
        Bhi += (size_t)bh * Ss * DKk; Blo += (size_t)bh * Ss * DKk;
        Pf  += (size_t)bh * Ss * Ss;
    }
    if (MODE == 4) {
        bh = blockIdx.z; b_ = bh >> 3; h_ = bh & 7;
        Pf  += (size_t)bh * Ss * Ss;
        Bhi += (size_t)bh * DKk * Ss; Blo += (size_t)bh * DKk * Ss;
    }

    const int m0 = blockIdx.y * 128;
    const int n0 = blockIdx.x * 64;
    const int tid = threadIdx.x;
    const int lane = tid & 31, wid = tid >> 5;
    const int warp_m = wid & 3, warp_n = wid >> 2;
    const int g = lane >> 2, tk = lane & 3;
    const int rr = lane & 7, q = lane >> 3;

    __shared__ uint32_t AsHi[128 * 20], AsLo[128 * 20];
    __shared__ uint32_t BsHi[64 * 20],  BsLo[64 * 20];
    const uint32_t sAhi = (uint32_t)__cvta_generic_to_shared(AsHi);
    const uint32_t sAlo = (uint32_t)__cvta_generic_to_shared(AsLo);
    const uint32_t sBhi = (uint32_t)__cvta_generic_to_shared(BsHi);
    const uint32_t sBlo = (uint32_t)__cvta_generic_to_shared(BsLo);

    // ldmatrix lane byte offsets
    const uint32_t offA0 = ((warp_m * 32 + (q & 1) * 8 + rr) * 20 + (q >> 1) * 4) * 4;
    const uint32_t offA1 = offA0 + 16 * 20 * 4;
    const uint32_t offB0 = ((warp_n * 32 + (q >> 1) * 8 + rr) * 20 + (q & 1) * 4) * 4;
    const uint32_t offB1 = offB0 + 16 * 20 * 4;

    float acc[2][4][4];
#pragma unroll
    for (int t = 0; t < 2; t++)
#pragma unroll
        for (int u = 0; u < 4; u++)
#pragma unroll
            for (int j = 0; j < 4; j++) acc[t][u][j] = 0.f;

    const int NC = K >> 5;

    // ---- prefetch registers ----
    uint4 pAh[2], pAl[2], pBh, pBl;   // plane paths
    float4 pa[4];                     // mode 4 A path
    int arow[4];
    float inva[4];

    if (MODE == 4) {
#pragma unroll
        for (int i = 0; i < 4; i++) {
            int v = tid + 256 * i;
            arow[i] = v >> 3;
            inva[i] = invl[bh * Ss + m0 + arow[i]];
        }
#pragma unroll
        for (int i = 0; i < 4; i++) {
            int v = tid + 256 * i, c4 = v & 7;
            pa[i] = *(const float4*)&Pf[(size_t)(m0 + arow[i]) * Ss + c4 * 4];
        }
    } else {
#pragma unroll
        for (int i = 0; i < 2; i++) {
            int v = tid + 256 * i, row = v >> 2, c = v & 3;
            pAh[i] = *((const uint4*)(Ahi + (size_t)(m0 + row) * lda) + c);
            pAl[i] = *((const uint4*)(Alo + (size_t)(m0 + row) * lda) + c);
        }
    }
    {
        int row = tid >> 2, c = tid & 3;
        pBh = *((const uint4*)(Bhi + (size_t)(n0 + row) * ldb) + c);
        pBl = *((const uint4*)(Blo + (size_t)(n0 + row) * ldb) + c);
    }

    for (int c = 0; c < NC; c++) {
        const int k0 = c * 32;
        // ---- store current chunk to smem ----
        if (MODE == 4) {
#pragma unroll
            for (int i = 0; i < 4; i++) {
                int v = tid + 256 * i, c4 = v & 7;
                float f0 = pa[i].x * inva[i], f1 = pa[i].y * inva[i];
                float f2 = pa[i].z * inva[i], f3 = pa[i].w * inva[i];
                *(float4*)&Pf[(size_t)(m0 + arow[i]) * Ss + k0 + c4 * 4] =
                    make_float4(f0, f1, f2, f3);
                int w = arow[i] * 20 + c4 * 2;
                hilo(f0, f1, AsHi[w], AsLo[w]);
                hilo(f2, f3, AsHi[w + 1], AsLo[w + 1]);
            }
        } else {
#pragma unroll
            for (int i = 0; i < 2; i++) {
                int v = tid + 256 * i, row = v >> 2, cc = v & 3;
                *(uint4*)&AsHi[row * 20 + cc * 4] = pAh[i];
                *(uint4*)&AsLo[row * 20 + cc * 4] = pAl[i];
            }
        }
        {
            int row = tid >> 2, cc = tid & 3;
            *(uint4*)&BsHi[row * 20 + cc * 4] = pBh;
            *(uint4*)&BsLo[row * 20 + cc * 4] = pBl;
        }
        __syncthreads();

        // ---- prefetch next chunk ----
        if (c + 1 < NC) {
            const int k1 = k0 + 32;
            if (MODE == 4) {
#pragma unroll
                for (int i = 0; i < 4; i++) {
                    int v = tid + 256 * i, c4 = v & 7;
                    pa[i] = *(const float4*)&Pf[(size_t)(m0 + arow[i]) * Ss + k1 + c4 * 4];
                }
            } else {
#pragma unroll
                for (int i = 0; i < 2; i++) {
                    int v = tid + 256 * i, row = v >> 2, cc = v & 3;
                    pAh[i] = *((const uint4*)(Ahi + (size_t)(m0 + row) * lda + k1) + cc);
                    pAl[i] = *((const uint4*)(Alo + (size_t)(m0 + row) * lda + k1) + cc);
                }
            }
            int row = tid >> 2, cc = tid & 3;
            pBh = *((const uint4*)(Bhi + (size_t)(n0 + row) * ldb + k1) + cc);
            pBl = *((const uint4*)(Blo + (size_t)(n0 + row) * ldb + k1) + cc);
        }

        mma_chunk(sAhi, sAlo, sBhi, sBlo, offA0, offA1, offB0, offB1, acc);
        __syncthreads();
    }

    // ---------------- epilogue ----------------
#pragma unroll
    for (int t = 0; t < 2; t++) {
#pragma unroll
        for (int half = 0; half < 2; half++) {
            const int m = m0 + warp_m * 32 + t * 16 + g + half * 8;
            float rsum = 0.f;
#pragma unroll
            for (int u = 0; u < 4; u++) {
                const int n = n0 + warp_n * 32 + u * 8 + tk * 2;
                float v0 = acc[t][u][half * 2 + 0];
                float v1 = acc[t][u][half * 2 + 1];
                if (MODE == 0) {
                    int b = m >> 11, s = m & 2047;
                    int h = n >> 6, dk = n & 63;
                    size_t idx = ((size_t)(b * Hh + h) * Ss + s) * DKk + dk;
                    uint32_t hw, lw;
                    hilo(v0, v1, hw, lw);
                    ((uint32_t*)Ohi)[idx >> 1] = hw;
                    ((uint32_t*)Olo)[idx >> 1] = lw;
                } else if (MODE == 1) {
                    int b = m >> 11, s = m & 2047;
                    int h = n >> 6, dk = n & 63;
                    size_t i0 = ((size_t)(b * Hh + h) * DKk + dk) * Ss + s;
                    __nv_bfloat16 h0 = __float2bfloat16(v0);
                    __nv_bfloat16 h1 = __float2bfloat16(v1);
                    Ohi[i0] = h0;
                    Olo[i0] = __float2bfloat16(v0 - __bfloat162float(h0));
                    Ohi[i0 + Ss] = h1;
                    Olo[i0 + Ss] = __float2bfloat16(v1 - __bfloat162float(h1));
                } else if (MODE == 2) {
                    *(float2*)&Cf[(size_t)m * Dd + n] = make_float2(v0, v1);
                } else if (MODE == 3) {
                    float p0 = __expf(v0 * SCALE);
                    float p1 = __expf(v1 * SCALE);
                    *(float2*)&Pf[(size_t)m * Ss + n] = make_float2(p0, p1);
                    rsum += p0 + p1;
                } else {  // MODE 4
                    size_t idx = ((size_t)(b_ * Ss + m)) * Dd + h_ * DKk + n;
                    uint32_t hw, lw;
                    hilo(v0, v1, hw, lw);
                    ((uint32_t*)Ohi)[idx >> 1] = hw;
                    ((uint32_t*)Olo)[idx >> 1] = lw;
                }
            }
            if (MODE == 3) {
                rsum += __shfl_xor_sync(0xffffffffu, rsum, 1);
                rsum += __shfl_xor_sync(0xffffffffu, rsum, 2);
                if (tk == 0)
                    lpart[((size_t)(bh * Ss + m)) * 64 + blockIdx.x * 2 + warp_n] = rsum;
            }
        }
    }
}

// ---------------- reduce partial sums -> 1/l ----------------
__global__ __launch_bounds__(256) void reduce_l(const float* __restrict__ lpart,
                                                float* __restrict__ invl)
{
    int i = blockIdx.x * 256 + threadIdx.x;
    const float* p = lpart + (size_t)i * 64;
    float s = 0.f;
#pragma unroll
    for (int j = 0; j < 64; j++) s += p[j];
    invl[i] = 1.f / s;
}

// ---------------- launch ----------------
extern "C" void kernel_launch(void* const* d_in, const int* in_sizes, int n_in,
                              void* d_out, int out_size)
{
    const float* inx[3] = {(const float*)d_in[0], (const float*)d_in[1], (const float*)d_in[2]};
    const float* wx[4]  = {(const float*)d_in[3], (const float*)d_in[4],
                           (const float*)d_in[5], (const float*)d_in[6]};

    float* out_main = (float*)d_out;
    float* p_attn   = out_main + (size_t)MM * Dd;

    __nv_bfloat16 *inhi, *inlo, *whi, *wlo, *Qhi, *Qlo, *Khi, *Klo, *Vthi, *Vtlo, *Ohi, *Olo;
    float *Lp, *Ip;
    cudaGetSymbolAddress((void**)&inhi, g_in_hi);
    cudaGetSymbolAddress((void**)&inlo, g_in_lo);
    cudaGetSymbolAddress((void**)&whi,  g_w_hi);
    cudaGetSymbolAddress((void**)&wlo,  g_w_lo);
    cudaGetSymbolAddress((void**)&Qhi,  g_Qhi);
    cudaGetSymbolAddress((void**)&Qlo,  g_Qlo);
    cudaGetSymbolAddress((void**)&Khi,  g_Khi);
    cudaGetSymbolAddress((void**)&Klo,  g_Klo);
    cudaGetSymbolAddress((void**)&Vthi, g_Vthi);
    cudaGetSymbolAddress((void**)&Vtlo, g_Vtlo);
    cudaGetSymbolAddress((void**)&Ohi,  g_Ohi);
    cudaGetSymbolAddress((void**)&Olo,  g_Olo);
    cudaGetSymbolAddress((void**)&Lp,   g_lpart);
    cudaGetSymbolAddress((void**)&Ip,   g_invl);

    // pre-convert inputs and weights to bf16 hi/lo planes
    for (int i = 0; i < 3; i++)
        conv_hilo<<<(MM * Dd) / 1024, 256>>>(inx[i], inhi + (size_t)i * MM * Dd,
                                             inlo + (size_t)i * MM * Dd);
    for (int i = 0; i < 4; i++)
        conv_hilo<<<(Dd * Dd) / 1024, 256>>>(wx[i], whi + (size_t)i * Dd * Dd,
                                             wlo + (size_t)i * Dd * Dd);

    dim3 pj_grid(Dd / 64, MM / 128);   // (8, 32)
    // Q projection
    gemm_k<0><<<pj_grid, 256>>>(inhi, inlo, whi, wlo,
                                nullptr, nullptr, Qhi, Qlo, nullptr, nullptr, Dd, Dd, Dd);
    // K projection
    gemm_k<0><<<pj_grid, 256>>>(inhi + (size_t)1 * MM * Dd, inlo + (size_t)1 * MM * Dd,
                                whi + (size_t)1 * Dd * Dd, wlo + (size_t)1 * Dd * Dd,
                                nullptr, nullptr, Khi, Klo, nullptr, nullptr, Dd, Dd, Dd);
    // V projection -> Vt planes
    gemm_k<1><<<pj_grid, 256>>>(inhi + (size_t)2 * MM * Dd, inlo + (size_t)2 * MM * Dd,
                                whi + (size_t)2 * Dd * Dd, wlo + (size_t)2 * Dd * Dd,
                                nullptr, nullptr, Vthi, Vtlo, nullptr, nullptr, Dd, Dd, Dd);

    dim3 sc_grid(Ss / 64, Ss / 128, BH);   // (32, 16, 16)
    gemm_k<3><<<sc_grid, 256>>>(Qhi, Qlo, Khi, Klo,
                                p_attn, nullptr, nullptr, nullptr, nullptr, Lp,
                                DKk, DKk, DKk);

    reduce_l<<<(BH * Ss) / 256, 256>>>(Lp, Ip);

    dim3 pv_grid(1, Ss / 128, BH);         // (1, 16, 16)
    gemm_k<4><<<pv_grid, 256>>>(nullptr, nullptr, Vthi, Vtlo,
                                p_attn, nullptr, Ohi, Olo, Ip, nullptr,
                                Ss, Ss, Ss);

    // final projection (f32 out)
    gemm_k<2><<<pj_grid, 256>>>(Ohi, Olo, whi + (size_t)3 * Dd * Dd, wlo + (size_t)3 * Dd * Dd,
                                nullptr, out_main, nullptr, nullptr, nullptr, nullptr,
                                Dd, Dd, Dd);
}

// round 8
// speedup vs baseline: 1.1537x; 1.1537x over previous
#include <cuda_runtime.h>
#include <cstdint>
#include <cstddef>

#define Ss 2048
#define Dd 512
#define Hh 8
#define DKk 64
#define BH 16
#define MM 4096
#define SCALE 0.125f

// ---------------- scratch (device globals; no allocation allowed) ----------------
__device__ float g_Q[BH * Ss * DKk];     // [b,h,s,dk]
__device__ float g_K[BH * Ss * DKk];     // [b,h,s,dk]
__device__ float g_Vt[BH * DKk * Ss];    // [b,h,dk,s]
__device__ float g_O[MM * Dd];           // merged heads [b,s,d]
__device__ float g_lpart[BH * Ss * 64];
__device__ float g_invl[BH * Ss];

// ---------------- helpers ----------------
__device__ __forceinline__ uint32_t f2tf(float x) {
    uint32_t r;
    asm("cvt.rna.tf32.f32 %0, %1;" : "=r"(r) : "f"(x));
    return r;
}
__device__ __forceinline__ void mma_tf32(float& c0, float& c1, float& c2, float& c3,
                                         uint32_t a0, uint32_t a1, uint32_t a2, uint32_t a3,
                                         uint32_t b0, uint32_t b1) {
    asm volatile(
        "mma.sync.aligned.m16n8k8.row.col.f32.tf32.tf32.f32 "
        "{%0,%1,%2,%3}, {%4,%5,%6,%7}, {%8,%9}, {%0,%1,%2,%3};"
        : "+f"(c0), "+f"(c1), "+f"(c2), "+f"(c3)
        : "r"(a0), "r"(a1), "r"(a2), "r"(a3), "r"(b0), "r"(b1));
}

#define LDA 36   // smem row stride in words (32 data + 4 pad; conflict-free)

// =====================================================================
// Unified GEMM: C[m,n] = sum_k A[m,k] * B[n,k]   (both k-contiguous, f32)
// Block tile 128x64, KT=32 chunks, 8 warps (4m x 2n), warp tile 32x32.
// MODE 0: -> head-split f32 [b,h,s,dk]
// MODE 1: -> Vt f32 [b,h,dk,s]
// MODE 2: -> plain f32 [m, Dd]
// MODE 3: per-bh scores -> P~ = exp(s/8) + lpart
// MODE 4: per-bh PV, A = P~ (normalize + writeback), -> O f32 merged
// =====================================================================
template <int MODE>
__global__ __launch_bounds__(256, 2) void gemm_k(
    const float* __restrict__ A, const float* __restrict__ B,
    float* __restrict__ Pf, float* __restrict__ Out,
    const float* __restrict__ invl, float* __restrict__ lpart,
    int K, int lda, int ldb)
{
    int bh = 0, b_ = 0, h_ = 0;
    if (MODE == 3) {
        bh = blockIdx.z;
        A += (size_t)bh * Ss * DKk;
        B += (size_t)bh * Ss * DKk;
        Pf += (size_t)bh * Ss * Ss;
    }
    if (MODE == 4) {
        bh = blockIdx.z; b_ = bh >> 3; h_ = bh & 7;
        Pf += (size_t)bh * Ss * Ss;
        B  += (size_t)bh * DKk * Ss;
    }

    const int m0 = blockIdx.y * 128;
    const int n0 = blockIdx.x * 64;
    const int tid = threadIdx.x;
    const int lane = tid & 31, wid = tid >> 5;
    const int warp_m = wid & 3, warp_n = wid >> 2;
    const int g = lane >> 2, tk = lane & 3;

    __shared__ uint32_t As[128 * LDA];
    __shared__ uint32_t Bs[64 * LDA];

    float acc[2][4][4];
#pragma unroll
    for (int t = 0; t < 2; t++)
#pragma unroll
        for (int u = 0; u < 4; u++)
#pragma unroll
            for (int j = 0; j < 4; j++) acc[t][u][j] = 0.f;

    const int NC = K >> 5;

    // ---- prefetch state ----
    float4 pa[4], pb[2];
    int arow[4];
    float inva[4];
#pragma unroll
    for (int i = 0; i < 4; i++) {
        int v = tid + 256 * i;
        arow[i] = v >> 3;
    }
    if (MODE == 4) {
#pragma unroll
        for (int i = 0; i < 4; i++) inva[i] = invl[bh * Ss + m0 + arow[i]];
    }

    if (MODE == 4) {
#pragma unroll
        for (int i = 0; i < 4; i++) {
            int c4 = (tid + 256 * i) & 7;
            pa[i] = *(const float4*)&Pf[(size_t)(m0 + arow[i]) * Ss + c4 * 4];
        }
    } else {
#pragma unroll
        for (int i = 0; i < 4; i++) {
            int c4 = (tid + 256 * i) & 7;
            pa[i] = *(const float4*)&A[(size_t)(m0 + arow[i]) * lda + c4 * 4];
        }
    }
#pragma unroll
    for (int i = 0; i < 2; i++) {
        int v = tid + 256 * i, row = v >> 3, c4 = v & 7;
        pb[i] = *(const float4*)&B[(size_t)(n0 + row) * ldb + c4 * 4];
    }

    for (int c = 0; c < NC; c++) {
        const int k0 = c * 32;
        // ---- store chunk to smem (cvt to tf32) ----
#pragma unroll
        for (int i = 0; i < 4; i++) {
            int c4 = (tid + 256 * i) & 7;
            float f0 = pa[i].x, f1 = pa[i].y, f2 = pa[i].z, f3 = pa[i].w;
            if (MODE == 4) {
                f0 *= inva[i]; f1 *= inva[i]; f2 *= inva[i]; f3 *= inva[i];
                *(float4*)&Pf[(size_t)(m0 + arow[i]) * Ss + k0 + c4 * 4] =
                    make_float4(f0, f1, f2, f3);
            }
            uint32_t* w = &As[arow[i] * LDA + c4 * 4];
            w[0] = f2tf(f0); w[1] = f2tf(f1); w[2] = f2tf(f2); w[3] = f2tf(f3);
        }
#pragma unroll
        for (int i = 0; i < 2; i++) {
            int v = tid + 256 * i, row = v >> 3, c4 = v & 7;
            uint32_t* w = &Bs[row * LDA + c4 * 4];
            w[0] = f2tf(pb[i].x); w[1] = f2tf(pb[i].y);
            w[2] = f2tf(pb[i].z); w[3] = f2tf(pb[i].w);
        }
        __syncthreads();

        // ---- prefetch next chunk ----
        if (c + 1 < NC) {
            const int k1 = k0 + 32;
            if (MODE == 4) {
#pragma unroll
                for (int i = 0; i < 4; i++) {
                    int c4 = (tid + 256 * i) & 7;
                    pa[i] = *(const float4*)&Pf[(size_t)(m0 + arow[i]) * Ss + k1 + c4 * 4];
                }
            } else {
#pragma unroll
                for (int i = 0; i < 4; i++) {
                    int c4 = (tid + 256 * i) & 7;
                    pa[i] = *(const float4*)&A[(size_t)(m0 + arow[i]) * lda + k1 + c4 * 4];
                }
            }
#pragma unroll
            for (int i = 0; i < 2; i++) {
                int v = tid + 256 * i, row = v >> 3, c4 = v & 7;
                pb[i] = *(const float4*)&B[(size_t)(n0 + row) * ldb + k1 + c4 * 4];
            }
        }

        // ---- compute: 4 k8 steps ----
#pragma unroll
        for (int s = 0; s < 4; s++) {
            const int ks = s * 8;
            uint32_t af[2][4];
#pragma unroll
            for (int t = 0; t < 2; t++) {
                int r = (warp_m * 32 + t * 16 + g) * LDA + ks + tk;
                af[t][0] = As[r];
                af[t][1] = As[r + 8 * LDA];
                af[t][2] = As[r + 4];
                af[t][3] = As[r + 8 * LDA + 4];
            }
            uint32_t bf[4][2];
#pragma unroll
            for (int u = 0; u < 4; u++) {
                int r = (warp_n * 32 + u * 8 + g) * LDA + ks + tk;
                bf[u][0] = Bs[r];
                bf[u][1] = Bs[r + 4];
            }
#pragma unroll
            for (int t = 0; t < 2; t++)
#pragma unroll
                for (int u = 0; u < 4; u++) {
                    float* cc = acc[t][u];
                    mma_tf32(cc[0], cc[1], cc[2], cc[3],
                             af[t][0], af[t][1], af[t][2], af[t][3],
                             bf[u][0], bf[u][1]);
                }
        }
        __syncthreads();
    }

    // ---------------- epilogue ----------------
#pragma unroll
    for (int t = 0; t < 2; t++) {
#pragma unroll
        for (int half = 0; half < 2; half++) {
            const int m = m0 + warp_m * 32 + t * 16 + g + half * 8;
            float rsum = 0.f;
#pragma unroll
            for (int u = 0; u < 4; u++) {
                const int n = n0 + warp_n * 32 + u * 8 + tk * 2;
                float v0 = acc[t][u][half * 2 + 0];
                float v1 = acc[t][u][half * 2 + 1];
                if (MODE == 0) {
                    int b = m >> 11, s = m & 2047;
                    int h = n >> 6, dk = n & 63;
                    *(float2*)&Out[(((size_t)(b * Hh + h) * Ss + s) * DKk) + dk] =
                        make_float2(v0, v1);
                } else if (MODE == 1) {
                    int b = m >> 11, s = m & 2047;
                    int h = n >> 6, dk = n & 63;
                    size_t i0 = ((size_t)(b * Hh + h) * DKk + dk) * Ss + s;
                    Out[i0] = v0;
                    Out[i0 + Ss] = v1;
                } else if (MODE == 2) {
                    *(float2*)&Out[(size_t)m * Dd + n] = make_float2(v0, v1);
                } else if (MODE == 3) {
                    float p0 = __expf(v0 * SCALE);
                    float p1 = __expf(v1 * SCALE);
                    *(float2*)&Pf[(size_t)m * Ss + n] = make_float2(p0, p1);
                    rsum += p0 + p1;
                } else {  // MODE 4
                    *(float2*)&Out[((size_t)(b_ * Ss + m)) * Dd + h_ * DKk + n] =
                        make_float2(v0, v1);
                }
            }
            if (MODE == 3) {
                rsum += __shfl_xor_sync(0xffffffffu, rsum, 1);
                rsum += __shfl_xor_sync(0xffffffffu, rsum, 2);
                if (tk == 0)
                    lpart[((size_t)(bh * Ss + m)) * 64 + blockIdx.x * 2 + warp_n] = rsum;
            }
        }
    }
}

// ---------------- reduce partial sums -> 1/l ----------------
__global__ __launch_bounds__(256) void reduce_l(const float* __restrict__ lpart,
                                                float* __restrict__ invl)
{
    int i = blockIdx.x * 256 + threadIdx.x;
    const float* p = lpart + (size_t)i * 64;
    float s = 0.f;
#pragma unroll
    for (int j = 0; j < 64; j++) s += p[j];
    invl[i] = 1.f / s;
}

// ---------------- launch ----------------
extern "C" void kernel_launch(void* const* d_in, const int* in_sizes, int n_in,
                              void* d_out, int out_size)
{
    const float* query = (const float*)d_in[0];
    const float* key   = (const float*)d_in[1];
    const float* value = (const float*)d_in[2];
    const float* w_q   = (const float*)d_in[3];
    const float* w_k   = (const float*)d_in[4];
    const float* w_v   = (const float*)d_in[5];
    const float* w_o   = (const float*)d_in[6];

    float* out_main = (float*)d_out;
    float* p_attn   = out_main + (size_t)MM * Dd;

    float *Qp, *Kp, *Vp, *Op, *Lp, *Ip;
    cudaGetSymbolAddress((void**)&Qp, g_Q);
    cudaGetSymbolAddress((void**)&Kp, g_K);
    cudaGetSymbolAddress((void**)&Vp, g_Vt);
    cudaGetSymbolAddress((void**)&Op, g_O);
    cudaGetSymbolAddress((void**)&Lp, g_lpart);
    cudaGetSymbolAddress((void**)&Ip, g_invl);

    dim3 pj_grid(Dd / 64, MM / 128);   // (8, 32)
    gemm_k<0><<<pj_grid, 256>>>(query, w_q, nullptr, Qp, nullptr, nullptr, Dd, Dd, Dd);
    gemm_k<0><<<pj_grid, 256>>>(key,   w_k, nullptr, Kp, nullptr, nullptr, Dd, Dd, Dd);
    gemm_k<1><<<pj_grid, 256>>>(value, w_v, nullptr, Vp, nullptr, nullptr, Dd, Dd, Dd);

    dim3 sc_grid(Ss / 64, Ss / 128, BH);   // (32, 16, 16)
    gemm_k<3><<<sc_grid, 256>>>(Qp, Kp, p_attn, nullptr, nullptr, Lp, DKk, DKk, DKk);

    reduce_l<<<(BH * Ss) / 256, 256>>>(Lp, Ip);

    dim3 pv_grid(1, Ss / 128, BH);         // (1, 16, 16)
    gemm_k<4><<<pv_grid, 256>>>(nullptr, Vp, p_attn, Op, Ip, nullptr, Ss, Ss, Ss);

    gemm_k<2><<<pj_grid, 256>>>(Op, w_o, nullptr, out_main, nullptr, nullptr, Dd, Dd, Dd);
}